// round 8
// baseline (speedup 1.0000x reference)
#include <cuda_runtime.h>
#include <cuda_bf16.h>

// bow_labeler: masked mean-pool over L, then 14 small linear heads (54 outputs).
// B=256, L=512, D=768.
// K1: masked partial column sums over 64-row L-chunks (BW-bound stream,
//     ~5.4 TB/s on valid traffic = measured ceiling for this skip pattern).
// K2: per-batch epilogue — reduce 8 partials + count + normalize + 54-head
//     GEMV, all in one kernel (256 blocks x 512 threads).

#define B_DIM   256
#define L_DIM   512
#define D_DIM   768
#define N_OUT   54
#define SPLIT   8
#define L_CHUNK (L_DIM / SPLIT)   // 64
#define D4      (D_DIM / 4)       // 192 float4 per row
#define T1      192
#define T2      512

__device__ float g_partial[B_DIM * SPLIT * D_DIM];   // 6 MB

__device__ __forceinline__ void f4acc(float4& a, const float4& v) {
    a.x += v.x; a.y += v.y; a.z += v.z; a.w += v.w;
}

// ---------------- K1: masked partial sums ----------------
__global__ __launch_bounds__(T1) void pool_partial_kernel(
    const float* __restrict__ fh,
    const int*   __restrict__ mask)
{
    const int s  = blockIdx.x;
    const int b  = blockIdx.y;
    const int c4 = threadIdx.x;   // float4 column 0..191

    __shared__ int s_mask[L_CHUNK];
    if (c4 < L_CHUNK) s_mask[c4] = mask[b * L_DIM + s * L_CHUNK + c4];
    __syncthreads();

    const float4* base =
        (const float4*)(fh + ((size_t)b * L_DIM + (size_t)s * L_CHUNK) * D_DIM) + c4;

    // 64 rows per chunk; 8 guarded independent 16B loads per unrolled body.
    float4 a0 = make_float4(0.f,0.f,0.f,0.f);
    float4 a1 = make_float4(0.f,0.f,0.f,0.f);
    float4 a2 = make_float4(0.f,0.f,0.f,0.f);
    float4 a3 = make_float4(0.f,0.f,0.f,0.f);
    #pragma unroll 1
    for (int l = 0; l < L_CHUNK; l += 8) {
        if (s_mask[l+0]) f4acc(a0, base[(size_t)(l+0) * D4]);
        if (s_mask[l+1]) f4acc(a1, base[(size_t)(l+1) * D4]);
        if (s_mask[l+2]) f4acc(a2, base[(size_t)(l+2) * D4]);
        if (s_mask[l+3]) f4acc(a3, base[(size_t)(l+3) * D4]);
        if (s_mask[l+4]) f4acc(a0, base[(size_t)(l+4) * D4]);
        if (s_mask[l+5]) f4acc(a1, base[(size_t)(l+5) * D4]);
        if (s_mask[l+6]) f4acc(a2, base[(size_t)(l+6) * D4]);
        if (s_mask[l+7]) f4acc(a3, base[(size_t)(l+7) * D4]);
    }
    f4acc(a0, a1); f4acc(a2, a3); f4acc(a0, a2);

    ((float4*)(g_partial + ((size_t)b * SPLIT + s) * D_DIM))[c4] = a0;
}

// ---------------- K2: fused reduce + normalize + heads ----------------
__global__ __launch_bounds__(T2) void epilogue_kernel(
    const int*   __restrict__ mask,
    const float* __restrict__ W13,
    const float* __restrict__ b13,
    const float* __restrict__ W14,
    const float* __restrict__ b14,
    float*       __restrict__ out)
{
    const int b    = blockIdx.x;
    const int tid  = threadIdx.x;
    const int lane = tid & 31;
    const int warp = tid >> 5;

    __shared__ float4 s_pooled[D4];   // 3 KB
    __shared__ int    s_cnt;
    __shared__ float  s_inv;

    if (tid == 0) s_cnt = 0;
    __syncthreads();

    // Count valid tokens: 512 threads, one mask element each.
    {
        int m = mask[b * L_DIM + tid];
        #pragma unroll
        for (int off = 16; off; off >>= 1)
            m += __shfl_down_sync(0xffffffffu, m, off);
        if (lane == 0) atomicAdd(&s_cnt, m);
    }

    // Threads 0..191 reduce the 8 partials for their float4 column
    // (8 independent 16B loads in flight each).
    float4 cs = make_float4(0.f,0.f,0.f,0.f);
    if (tid < D4) {
        const float4* gp4 = (const float4*)(g_partial + (size_t)b * SPLIT * D_DIM);
        #pragma unroll
        for (int s = 0; s < SPLIT; s++)
            f4acc(cs, gp4[(size_t)s * D4 + tid]);
    }

    __syncthreads();
    if (tid == 0) s_inv = 1.0f / (float)s_cnt;
    __syncthreads();

    if (tid < D4) {
        float inv = s_inv;
        cs.x *= inv; cs.y *= inv; cs.z *= inv; cs.w *= inv;
        s_pooled[tid] = cs;
    }
    __syncthreads();

    // 54 dot-products over 16 warps (first 6 warps do 4, rest do 3).
    // Weight rows (166 KB total) stay L1-resident across blocks on an SM.
    for (int o = warp; o < N_OUT; o += (T2 / 32)) {
        const float4* w4 = (const float4*)((o < 52) ? (W13 + (size_t)o * D_DIM)
                                                    : (W14 + (size_t)(o - 52) * D_DIM));
        const float bias = (o < 52) ? b13[o] : b14[o - 52];
        float acc = 0.f;
        #pragma unroll
        for (int i = 0; i < D4 / 32; i++) {
            float4 w = w4[lane + 32 * i];
            float4 p = s_pooled[lane + 32 * i];
            acc += w.x * p.x + w.y * p.y + w.z * p.z + w.w * p.w;
        }
        #pragma unroll
        for (int off = 16; off; off >>= 1)
            acc += __shfl_down_sync(0xffffffffu, acc, off);
        if (lane == 0) out[b * N_OUT + o] = acc + bias;
    }
}

extern "C" void kernel_launch(void* const* d_in, const int* in_sizes, int n_in,
                              void* d_out, int out_size)
{
    const float* fh   = (const float*)d_in[0];
    const int*   mask = (const int*)d_in[1];
    const float* W13  = (const float*)d_in[2];
    const float* b13  = (const float*)d_in[3];
    const float* W14  = (const float*)d_in[4];
    const float* b14  = (const float*)d_in[5];
    float* out = (float*)d_out;

    dim3 grid1(SPLIT, B_DIM);
    pool_partial_kernel<<<grid1, T1>>>(fh, mask);
    epilogue_kernel<<<B_DIM, T2>>>(mask, W13, b13, W14, b14, out);
}

// round 9
// speedup vs baseline: 1.0007x; 1.0007x over previous
#include <cuda_runtime.h>
#include <cuda_bf16.h>

// bow_labeler: masked mean-pool over L, then 14 small linear heads (54 outputs).
// B=256, L=512, D=768.
// K1: masked partial column sums, grid (SPLIT, B) so concurrent blocks span
//     batches (better DRAM page/channel spread; measured ~34us).
// K2: reduce 8 partials + count + normalize -> g_pooled. PDL: mask count runs
//     under K1's tail.
// K3: batch-tiled heads (4 batches/block, 64x4 grid, weights register-
//     resident). PDL: weight loads run under K2.

#define B_DIM   256
#define L_DIM   512
#define D_DIM   768
#define N_OUT   54
#define SPLIT   8
#define L_CHUNK (L_DIM / SPLIT)   // 64
#define D4      (D_DIM / 4)       // 192 float4 per row
#define T1      192
#define T2      192
#define T3      512
#define BPB     4                 // batches per heads block
#define NBG     (B_DIM / BPB)     // 64 batch groups
#define OGRP    4                 // output groups
#define OPG     14                // outputs per group (last group: 12)

__device__ float g_partial[B_DIM * SPLIT * D_DIM];   // 6 MB
__device__ float g_pooled[B_DIM * D_DIM];            // 0.75 MB

__device__ __forceinline__ void f4acc(float4& a, const float4& v) {
    a.x += v.x; a.y += v.y; a.z += v.z; a.w += v.w;
}

// ---------------- K1: masked partial sums ----------------
__global__ __launch_bounds__(T1) void pool_partial_kernel(
    const float* __restrict__ fh,
    const int*   __restrict__ mask)
{
    const int s  = blockIdx.x;
    const int b  = blockIdx.y;
    const int c4 = threadIdx.x;   // float4 column 0..191

    __shared__ int s_mask[L_CHUNK];
    if (c4 < L_CHUNK) s_mask[c4] = mask[b * L_DIM + s * L_CHUNK + c4];
    __syncthreads();

    const float4* base =
        (const float4*)(fh + ((size_t)b * L_DIM + (size_t)s * L_CHUNK) * D_DIM) + c4;

    float4 a0 = make_float4(0.f,0.f,0.f,0.f);
    float4 a1 = make_float4(0.f,0.f,0.f,0.f);
    float4 a2 = make_float4(0.f,0.f,0.f,0.f);
    float4 a3 = make_float4(0.f,0.f,0.f,0.f);
    #pragma unroll 1
    for (int l = 0; l < L_CHUNK; l += 8) {
        if (s_mask[l+0]) f4acc(a0, base[(size_t)(l+0) * D4]);
        if (s_mask[l+1]) f4acc(a1, base[(size_t)(l+1) * D4]);
        if (s_mask[l+2]) f4acc(a2, base[(size_t)(l+2) * D4]);
        if (s_mask[l+3]) f4acc(a3, base[(size_t)(l+3) * D4]);
        if (s_mask[l+4]) f4acc(a0, base[(size_t)(l+4) * D4]);
        if (s_mask[l+5]) f4acc(a1, base[(size_t)(l+5) * D4]);
        if (s_mask[l+6]) f4acc(a2, base[(size_t)(l+6) * D4]);
        if (s_mask[l+7]) f4acc(a3, base[(size_t)(l+7) * D4]);
    }
    f4acc(a0, a1); f4acc(a2, a3); f4acc(a0, a2);

    ((float4*)(g_partial + ((size_t)b * SPLIT + s) * D_DIM))[c4] = a0;
}

// ---------------- K2: reduce partials + normalize (PDL secondary) ----------
__global__ __launch_bounds__(T2) void pool_reduce_kernel(
    const int* __restrict__ mask)
{
    const int b    = blockIdx.x;
    const int tid  = threadIdx.x;      // float4 column 0..191
    const int lane = tid & 31;

    __shared__ int   s_cnt;
    __shared__ float s_inv;

    if (tid == 0) s_cnt = 0;
    __syncthreads();

    // Pre-sync work (independent of K1): count valid tokens.
    {
        const int* mrow = mask + b * L_DIM;
        int m = mrow[tid] + mrow[tid + 192] + ((tid < 128) ? mrow[tid + 384] : 0);
        #pragma unroll
        for (int off = 16; off; off >>= 1)
            m += __shfl_down_sync(0xffffffffu, m, off);
        if (lane == 0) atomicAdd(&s_cnt, m);
    }

    // Wait for K1's partials to be globally visible.
    cudaGridDependencySynchronize();

    const float4* gp4 = (const float4*)(g_partial + (size_t)b * SPLIT * D_DIM);
    float4 cs = make_float4(0.f,0.f,0.f,0.f);
    #pragma unroll
    for (int s = 0; s < SPLIT; s++)
        f4acc(cs, gp4[(size_t)s * D4 + tid]);

    __syncthreads();
    if (tid == 0) s_inv = 1.0f / (float)s_cnt;
    __syncthreads();

    float inv = s_inv;
    cs.x *= inv; cs.y *= inv; cs.z *= inv; cs.w *= inv;
    ((float4*)(g_pooled + (size_t)b * D_DIM))[tid] = cs;
}

// ---------------- K3: heads GEMV (PDL secondary) ----------------
__global__ __launch_bounds__(T3) void heads_kernel(
    const float* __restrict__ W13,
    const float* __restrict__ b13,
    const float* __restrict__ W14,
    const float* __restrict__ b14,
    float*       __restrict__ out)
{
    const int b0   = blockIdx.x * BPB;        // batch group
    const int og   = blockIdx.y;              // output group
    const int tid  = threadIdx.x;
    const int lane = tid & 31;
    const int warp = tid >> 5;

    __shared__ float4 s_pooled[BPB][D4];      // 12 KB

    const int o      = og * OPG + warp;
    const bool active = (warp < OPG) && (o < min((og + 1) * OPG, N_OUT));

    // Pre-sync work (independent of K2): pull weights into registers.
    float4 w[D4 / 32];
    float  bias = 0.f;
    if (active) {
        const float4* w4 = (const float4*)((o < 52) ? (W13 + (size_t)o * D_DIM)
                                                    : (W14 + (size_t)(o - 52) * D_DIM));
        bias = (o < 52) ? b13[o] : b14[o - 52];
        #pragma unroll
        for (int i = 0; i < D4 / 32; i++) w[i] = w4[lane + 32 * i];
    }

    cudaGridDependencySynchronize();

    // Stage 4 pooled vectors (768 float4, 512 threads -> 2 loads each).
    #pragma unroll
    for (int k = 0; k < 2; k++) {
        int idx = tid + T3 * k;
        if (idx < BPB * D4) {
            int bi = idx / D4, c4 = idx % D4;
            s_pooled[bi][c4] =
                ((const float4*)(g_pooled + (size_t)(b0 + bi) * D_DIM))[c4];
        }
    }
    __syncthreads();

    if (!active) return;

    float acc[BPB] = {0.f, 0.f, 0.f, 0.f};
    #pragma unroll
    for (int i = 0; i < D4 / 32; i++) {
        #pragma unroll
        for (int bi = 0; bi < BPB; bi++) {
            float4 p = s_pooled[bi][lane + 32 * i];
            acc[bi] += w[i].x * p.x + w[i].y * p.y + w[i].z * p.z + w[i].w * p.w;
        }
    }
    #pragma unroll
    for (int off = 16; off; off >>= 1) {
        #pragma unroll
        for (int bi = 0; bi < BPB; bi++)
            acc[bi] += __shfl_down_sync(0xffffffffu, acc[bi], off);
    }
    if (lane == 0) {
        #pragma unroll
        for (int bi = 0; bi < BPB; bi++)
            out[(b0 + bi) * N_OUT + o] = acc[bi] + bias;
    }
}

extern "C" void kernel_launch(void* const* d_in, const int* in_sizes, int n_in,
                              void* d_out, int out_size)
{
    const float* fh   = (const float*)d_in[0];
    const int*   mask = (const int*)d_in[1];
    const float* W13  = (const float*)d_in[2];
    const float* b13  = (const float*)d_in[3];
    const float* W14  = (const float*)d_in[4];
    const float* b14  = (const float*)d_in[5];
    float* out = (float*)d_out;

    dim3 grid1(SPLIT, B_DIM);
    pool_partial_kernel<<<grid1, T1>>>(fh, mask);

    cudaLaunchAttribute attr[1];
    attr[0].id = cudaLaunchAttributeProgrammaticStreamSerialization;
    attr[0].val.programmaticStreamSerializationAllowed = 1;

    {   // K2 with PDL
        cudaLaunchConfig_t cfg = {};
        cfg.gridDim = dim3(B_DIM);
        cfg.blockDim = dim3(T2);
        cfg.attrs = attr;
        cfg.numAttrs = 1;
        cudaLaunchKernelEx(&cfg, pool_reduce_kernel, mask);
    }
    {   // K3 with PDL
        cudaLaunchConfig_t cfg = {};
        cfg.gridDim = dim3(NBG, OGRP);
        cfg.blockDim = dim3(T3);
        cfg.attrs = attr;
        cfg.numAttrs = 1;
        cudaLaunchKernelEx(&cfg, heads_kernel, W13, b13, W14, b14, out);
    }
}